// round 2
// baseline (speedup 1.0000x reference)
#include <cuda_runtime.h>
#include <math.h>

#define HW 65536

__device__ float g_w2c[8 * 16];
__device__ int   g_idx[16 * HW];
__device__ int   g_cnt[16];
__device__ float g_wT[2 * 9 * 64 * 64];
__device__ float g_fused[8 * 64 * HW];
__device__ float g_mid[8 * 64 * HW];

__constant__ int c_pj[6] = {0, 1, 1, 2, 2, 3};
__constant__ int c_pk[6] = {1, 0, 2, 1, 3, 2};

__device__ __forceinline__ unsigned long long fma2(unsigned long long a,
                                                   unsigned long long b,
                                                   unsigned long long c) {
    unsigned long long d;
    asm("fma.rn.f32x2 %0, %1, %2, %3;" : "=l"(d) : "l"(a), "l"(b), "l"(c));
    return d;
}
__device__ __forceinline__ unsigned long long lds2(const float* p) {
    return *reinterpret_cast<const unsigned long long*>(p);
}

__global__ void setup_kernel(const float* __restrict__ extr,
                             const float* __restrict__ w1,
                             const float* __restrict__ w2) {
    int tid = threadIdx.x;
    if (tid < 16) g_cnt[tid] = 0;
    if (tid >= 64 && tid < 72) {
        const float* m = extr + (tid - 64) * 16;
        float inv[16];
        inv[0]  =  m[5]*m[10]*m[15] - m[5]*m[11]*m[14] - m[9]*m[6]*m[15] + m[9]*m[7]*m[14] + m[13]*m[6]*m[11] - m[13]*m[7]*m[10];
        inv[4]  = -m[4]*m[10]*m[15] + m[4]*m[11]*m[14] + m[8]*m[6]*m[15] - m[8]*m[7]*m[14] - m[12]*m[6]*m[11] + m[12]*m[7]*m[10];
        inv[8]  =  m[4]*m[9]*m[15]  - m[4]*m[11]*m[13] - m[8]*m[5]*m[15] + m[8]*m[7]*m[13] + m[12]*m[5]*m[11] - m[12]*m[7]*m[9];
        inv[12] = -m[4]*m[9]*m[14]  + m[4]*m[10]*m[13] + m[8]*m[5]*m[14] - m[8]*m[6]*m[13] - m[12]*m[5]*m[10] + m[12]*m[6]*m[9];
        inv[1]  = -m[1]*m[10]*m[15] + m[1]*m[11]*m[14] + m[9]*m[2]*m[15] - m[9]*m[3]*m[14] - m[13]*m[2]*m[11] + m[13]*m[3]*m[10];
        inv[5]  =  m[0]*m[10]*m[15] - m[0]*m[11]*m[14] - m[8]*m[2]*m[15] + m[8]*m[3]*m[14] + m[12]*m[2]*m[11] - m[12]*m[3]*m[10];
        inv[9]  = -m[0]*m[9]*m[15]  + m[0]*m[11]*m[13] + m[8]*m[1]*m[15] - m[8]*m[3]*m[13] - m[12]*m[1]*m[11] + m[12]*m[3]*m[9];
        inv[13] =  m[0]*m[9]*m[14]  - m[0]*m[10]*m[13] - m[8]*m[1]*m[14] + m[8]*m[2]*m[13] + m[12]*m[1]*m[10] - m[12]*m[2]*m[9];
        inv[2]  =  m[1]*m[6]*m[15]  - m[1]*m[7]*m[14]  - m[5]*m[2]*m[15] + m[5]*m[3]*m[14] + m[13]*m[2]*m[7]  - m[13]*m[3]*m[6];
        inv[6]  = -m[0]*m[6]*m[15]  + m[0]*m[7]*m[14]  + m[4]*m[2]*m[15] - m[4]*m[3]*m[14] - m[12]*m[2]*m[7]  + m[12]*m[3]*m[6];
        inv[10] =  m[0]*m[5]*m[15]  - m[0]*m[7]*m[13]  - m[4]*m[1]*m[15] + m[4]*m[3]*m[13] + m[12]*m[1]*m[7]  - m[12]*m[3]*m[5];
        inv[14] = -m[0]*m[5]*m[14]  + m[0]*m[6]*m[13]  + m[4]*m[1]*m[14] - m[4]*m[2]*m[13] - m[12]*m[1]*m[6]  + m[12]*m[2]*m[5];
        inv[3]  = -m[1]*m[6]*m[11]  + m[1]*m[7]*m[10]  + m[5]*m[2]*m[11] - m[5]*m[3]*m[10] - m[9]*m[2]*m[7]   + m[9]*m[3]*m[6];
        inv[7]  =  m[0]*m[6]*m[11]  - m[0]*m[7]*m[10]  - m[4]*m[2]*m[11] + m[4]*m[3]*m[10] + m[8]*m[2]*m[7]   - m[8]*m[3]*m[6];
        inv[11] = -m[0]*m[5]*m[11]  + m[0]*m[7]*m[9]   + m[4]*m[1]*m[11] - m[4]*m[3]*m[9]  - m[8]*m[1]*m[7]   + m[8]*m[3]*m[5];
        inv[15] =  m[0]*m[5]*m[10]  - m[0]*m[6]*m[9]   - m[4]*m[1]*m[10] + m[4]*m[2]*m[9]  + m[8]*m[1]*m[6]   - m[8]*m[2]*m[5];
        float det = m[0]*inv[0] + m[1]*inv[4] + m[2]*inv[8] + m[3]*inv[12];
        float rd = 1.0f / det;
        for (int n = 0; n < 16; n++) g_w2c[(tid - 64) * 16 + n] = inv[n] * rd;
    }
    for (int i = tid; i < 36864; i += blockDim.x) {
        int tap = i >> 12;
        int r = i & 4095;
        g_wT[i]         = w1[r * 9 + tap];
        g_wT[36864 + i] = w2[r * 9 + tap];
    }
}

__global__ void proj_kernel(const float* __restrict__ means,
                            const float* __restrict__ intrinsics) {
    int pi = blockIdx.y;
    int b = pi / 6, q = pi - b * 6;
    int j = c_pj[q], k = c_pk[q];
    int slot = (k < j) ? 0 : 1;
    int img = b * 4 + j;
    int pix = blockIdx.x * 256 + threadIdx.x;

    const float* m = means + ((long)img * HW + pix) * 3;
    float X = m[0], Y = m[1], Z = m[2];
    const float* w = g_w2c + (b * 4 + k) * 16;
    float c0 = w[0]*X + w[1]*Y + w[2]*Z  + w[3];
    float c1 = w[4]*X + w[5]*Y + w[6]*Z  + w[7];
    float c2 = w[8]*X + w[9]*Y + w[10]*Z + w[11];
    float dz = c2 + 1e-8f;
    float u0 = c0 / dz, u1 = c1 / dz, u2 = c2 / dz;
    const float* K = intrinsics + (b * 4 + k) * 9;
    float nx = K[0]*u0 + K[1]*u1 + K[2]*u2;
    float ny = K[3]*u0 + K[4]*u1 + K[5]*u2;
    bool mask = (nx >= 0.f) && (nx < 1.f) && (ny >= 0.f) && (ny < 1.f) && (c2 > 1e-8f);
    int px = (int)floorf(nx * 256.f);
    int py = (int)floorf(ny * 256.f);
    px = min(max(px, 0), 255);
    py = min(max(py, 0), 255);
    g_idx[(img * 2 + slot) * HW + pix] = mask ? (py * 256 + px) : -1;
    unsigned bal = __ballot_sync(0xFFFFFFFFu, mask);
    if ((threadIdx.x & 31) == 0)
        atomicAdd(&g_cnt[img * 2 + slot], __popc(bal));
}

__global__ void fuse_kernel(const float* __restrict__ feats) {
    const int img = blockIdx.y;
    const int j = img & 3;
    const int tid = threadIdx.x;
    const int pxl = tid & 63;
    const int chunk = tid >> 6;
    const int pix = (blockIdx.x << 6) + pxl;

    float s0 = 0.f, s1 = 0.f;
    int i0 = -1, i1 = -1;
    if (j > 0) {
        s0 = 0.1f * (float)g_cnt[img * 2 + 0] * (1.0f / 65536.f);
        i0 = g_idx[(img * 2 + 0) * HW + pix];
    }
    if (j < 3) {
        s1 = 0.1f * (float)g_cnt[img * 2 + 1] * (1.0f / 65536.f);
        i1 = g_idx[(img * 2 + 1) * HW + pix];
    }
    float rnorm = 1.f / (1.f + s0 + s1);

    const float4* sp = reinterpret_cast<const float4*>(feats + ((long)img * HW + pix) * 64 + (chunk << 4));
    float4 r[4];
#pragma unroll
    for (int q = 0; q < 4; q++) r[q] = sp[q];
    if (i0 >= 0) {
        const float4* gp = reinterpret_cast<const float4*>(feats + ((long)(img - 1) * HW + i0) * 64 + (chunk << 4));
#pragma unroll
        for (int q = 0; q < 4; q++) {
            float4 g = gp[q];
            r[q].x += s0 * g.x; r[q].y += s0 * g.y; r[q].z += s0 * g.z; r[q].w += s0 * g.w;
        }
    }
    if (i1 >= 0) {
        const float4* gp = reinterpret_cast<const float4*>(feats + ((long)(img + 1) * HW + i1) * 64 + (chunk << 4));
#pragma unroll
        for (int q = 0; q < 4; q++) {
            float4 g = gp[q];
            r[q].x += s1 * g.x; r[q].y += s1 * g.y; r[q].z += s1 * g.z; r[q].w += s1 * g.w;
        }
    }
    float* op = g_fused + ((long)img * 64 + (chunk << 4)) * HW + pix;
#pragma unroll
    for (int q = 0; q < 4; q++) {
        op[(q * 4 + 0) * HW] = r[q].x * rnorm;
        op[(q * 4 + 1) * HW] = r[q].y * rnorm;
        op[(q * 4 + 2) * HW] = r[q].z * rnorm;
        op[(q * 4 + 3) * HW] = r[q].w * rnorm;
    }
}

// 3x3 conv 64->64, FFMA2 register-tiled. MODE0: fused->gelu->mid. MODE1: mid->out(NHWC).
template <int MODE>
__global__ __launch_bounds__(256, 2) void conv_kernel(const float* __restrict__ bias,
                                                      float* __restrict__ outp) {
    const float* __restrict__ in = (MODE == 0) ? g_fused : g_mid;
    const float* __restrict__ wT = g_wT + MODE * 36864;
    extern __shared__ float sm[];
    float* in_s = sm;          // [(yy*18+xx)*66 + ci], yy<10, xx<18
    float* w_s = sm + 11880;   // [co*66+ci]

    const int tid = threadIdx.x;
    const int x = tid & 15;
    const int cog = tid >> 4;
    const int img = blockIdx.z;
    const int y0 = blockIdx.y * 8;
    const int x0 = blockIdx.x * 16;

    const float* inb = in + (long)img * 64 * HW;
    for (int i = tid; i < 64 * 180; i += 256) {
        int ci = i / 180;
        int r = i - ci * 180;
        int yy = r / 18;
        int xx = r - yy * 18;
        int gy = y0 - 1 + yy, gx = x0 - 1 + xx;
        float v = 0.f;
        if ((unsigned)gy < 256u && (unsigned)gx < 256u)
            v = inb[ci * HW + (gy << 8) + gx];
        in_s[(yy * 18 + xx) * 66 + ci] = v;
    }

    unsigned long long acc[4][8];
#pragma unroll
    for (int p = 0; p < 4; p++)
#pragma unroll
        for (int k = 0; k < 8; k++) acc[p][k] = 0ull;

    for (int tap = 0; tap < 9; ++tap) {
        __syncthreads();
        const float* wt = wT + tap * 4096;
        for (int i = tid; i < 4096; i += 256)
            w_s[(i >> 6) * 66 + (i & 63)] = wt[i];
        __syncthreads();
        const int dy = tap / 3 - 1;
        const int dx = tap - (tap / 3) * 3 - 1;
        const float* ir = in_s + ((1 + dy) * 18 + (1 + x + dx)) * 66;
        const float* wr = w_s + cog * 4 * 66;
#pragma unroll 2
        for (int ci = 0; ci < 64; ci += 2) {
            unsigned long long w0 = lds2(wr + ci);
            unsigned long long w1v = lds2(wr + 66 + ci);
            unsigned long long w2v = lds2(wr + 132 + ci);
            unsigned long long w3v = lds2(wr + 198 + ci);
            unsigned long long bv[8];
#pragma unroll
            for (int k = 0; k < 8; k++) bv[k] = lds2(ir + k * 1188 + ci);
#pragma unroll
            for (int k = 0; k < 8; k++) {
                acc[0][k] = fma2(w0, bv[k], acc[0][k]);
                acc[1][k] = fma2(w1v, bv[k], acc[1][k]);
                acc[2][k] = fma2(w2v, bv[k], acc[2][k]);
                acc[3][k] = fma2(w3v, bv[k], acc[3][k]);
            }
        }
    }

    if (MODE == 0) {
#pragma unroll
        for (int p = 0; p < 4; p++) {
            int co = cog * 4 + p;
            float bb = bias[co];
            float* ob = g_mid + ((long)img * 64 + co) * HW + (y0 << 8) + x0 + x;
#pragma unroll
            for (int k = 0; k < 8; k++) {
                float2 f = *reinterpret_cast<float2*>(&acc[p][k]);
                float v = f.x + f.y + bb;
                v = 0.5f * v * (1.0f + erff(v * 0.70710678118654752f));
                ob[k << 8] = v;
            }
        }
    } else {
        __syncthreads();
        float* st = sm; // [128 px][68]
#pragma unroll
        for (int p = 0; p < 4; p++) {
            int co = cog * 4 + p;
            float bb = bias[co];
#pragma unroll
            for (int k = 0; k < 8; k++) {
                float2 f = *reinterpret_cast<float2*>(&acc[p][k]);
                st[(k * 16 + x) * 68 + co] = f.x + f.y + bb;
            }
        }
        __syncthreads();
        const int lane = tid & 31, wrp = tid >> 5;
        for (int t = 0; t < 16; ++t) {
            int pxl = wrp * 16 + t;
            float2 v2 = *reinterpret_cast<float2*>(&st[pxl * 68 + lane * 2]);
            int py = pxl >> 4, pxx = pxl & 15;
            float* dst = outp + ((long)img * HW + ((y0 + py) << 8) + (x0 + pxx)) * 64 + lane * 2;
            *reinterpret_cast<float2*>(dst) = v2;
        }
    }
}

extern "C" void kernel_launch(void* const* d_in, const int* in_sizes, int n_in,
                              void* d_out, int out_size) {
    const float* means      = (const float*)d_in[0];
    const float* gs_feats   = (const float*)d_in[2];
    const float* intrinsics = (const float*)d_in[3];
    const float* extrinsics = (const float*)d_in[4];
    const float* w1 = (const float*)d_in[5];
    const float* b1 = (const float*)d_in[6];
    const float* w2 = (const float*)d_in[7];
    const float* b2 = (const float*)d_in[8];
    float* out = (float*)d_out;

    const int smem = 16104 * 4;
    cudaFuncSetAttribute(conv_kernel<0>, cudaFuncAttributeMaxDynamicSharedMemorySize, smem);
    cudaFuncSetAttribute(conv_kernel<1>, cudaFuncAttributeMaxDynamicSharedMemorySize, smem);

    setup_kernel<<<1, 256>>>(extrinsics, w1, w2);
    proj_kernel<<<dim3(256, 12), 256>>>(means, intrinsics);
    fuse_kernel<<<dim3(1024, 8), 256>>>(gs_feats);
    conv_kernel<0><<<dim3(16, 32, 8), 256, smem>>>(b1, out);
    conv_kernel<1><<<dim3(16, 32, 8), 256, smem>>>(b2, out);
}

// round 3
// speedup vs baseline: 1.0302x; 1.0302x over previous
#include <cuda_runtime.h>
#include <math.h>

#define HW 65536

__device__ float g_w2c[8 * 16];
__device__ int   g_idx[16 * HW];
__device__ int   g_cnt[16];
__device__ float g_wT[2 * 9 * 64 * 64];
__device__ float g_fused[8 * 64 * HW];
__device__ float g_mid[8 * 64 * HW];

__constant__ int c_pj[6] = {0, 1, 1, 2, 2, 3};
__constant__ int c_pk[6] = {1, 0, 2, 1, 3, 2};

__device__ __forceinline__ unsigned long long fma2(unsigned long long a,
                                                   unsigned long long b,
                                                   unsigned long long c) {
    unsigned long long d;
    asm("fma.rn.f32x2 %0, %1, %2, %3;" : "=l"(d) : "l"(a), "l"(b), "l"(c));
    return d;
}
__device__ __forceinline__ unsigned long long lds2(const float* p) {
    return *reinterpret_cast<const unsigned long long*>(p);
}

__global__ void setup_kernel(const float* __restrict__ extr,
                             const float* __restrict__ w1,
                             const float* __restrict__ w2) {
    int tid = threadIdx.x;
    if (tid < 16) g_cnt[tid] = 0;
    if (tid >= 64 && tid < 72) {
        const float* m = extr + (tid - 64) * 16;
        float inv[16];
        inv[0]  =  m[5]*m[10]*m[15] - m[5]*m[11]*m[14] - m[9]*m[6]*m[15] + m[9]*m[7]*m[14] + m[13]*m[6]*m[11] - m[13]*m[7]*m[10];
        inv[4]  = -m[4]*m[10]*m[15] + m[4]*m[11]*m[14] + m[8]*m[6]*m[15] - m[8]*m[7]*m[14] - m[12]*m[6]*m[11] + m[12]*m[7]*m[10];
        inv[8]  =  m[4]*m[9]*m[15]  - m[4]*m[11]*m[13] - m[8]*m[5]*m[15] + m[8]*m[7]*m[13] + m[12]*m[5]*m[11] - m[12]*m[7]*m[9];
        inv[12] = -m[4]*m[9]*m[14]  + m[4]*m[10]*m[13] + m[8]*m[5]*m[14] - m[8]*m[6]*m[13] - m[12]*m[5]*m[10] + m[12]*m[6]*m[9];
        inv[1]  = -m[1]*m[10]*m[15] + m[1]*m[11]*m[14] + m[9]*m[2]*m[15] - m[9]*m[3]*m[14] - m[13]*m[2]*m[11] + m[13]*m[3]*m[10];
        inv[5]  =  m[0]*m[10]*m[15] - m[0]*m[11]*m[14] - m[8]*m[2]*m[15] + m[8]*m[3]*m[14] + m[12]*m[2]*m[11] - m[12]*m[3]*m[10];
        inv[9]  = -m[0]*m[9]*m[15]  + m[0]*m[11]*m[13] + m[8]*m[1]*m[15] - m[8]*m[3]*m[13] - m[12]*m[1]*m[11] + m[12]*m[3]*m[9];
        inv[13] =  m[0]*m[9]*m[14]  - m[0]*m[10]*m[13] - m[8]*m[1]*m[14] + m[8]*m[2]*m[13] + m[12]*m[1]*m[10] - m[12]*m[2]*m[9];
        inv[2]  =  m[1]*m[6]*m[15]  - m[1]*m[7]*m[14]  - m[5]*m[2]*m[15] + m[5]*m[3]*m[14] + m[13]*m[2]*m[7]  - m[13]*m[3]*m[6];
        inv[6]  = -m[0]*m[6]*m[15]  + m[0]*m[7]*m[14]  + m[4]*m[2]*m[15] - m[4]*m[3]*m[14] - m[12]*m[2]*m[7]  + m[12]*m[3]*m[6];
        inv[10] =  m[0]*m[5]*m[15]  - m[0]*m[7]*m[13]  - m[4]*m[1]*m[15] + m[4]*m[3]*m[13] + m[12]*m[1]*m[7]  - m[12]*m[3]*m[5];
        inv[14] = -m[0]*m[5]*m[14]  + m[0]*m[6]*m[13]  + m[4]*m[1]*m[14] - m[4]*m[2]*m[13] - m[12]*m[1]*m[6]  + m[12]*m[2]*m[5];
        inv[3]  = -m[1]*m[6]*m[11]  + m[1]*m[7]*m[10]  + m[5]*m[2]*m[11] - m[5]*m[3]*m[10] - m[9]*m[2]*m[7]   + m[9]*m[3]*m[6];
        inv[7]  =  m[0]*m[6]*m[11]  - m[0]*m[7]*m[10]  - m[4]*m[2]*m[11] + m[4]*m[3]*m[10] + m[8]*m[2]*m[7]   - m[8]*m[3]*m[6];
        inv[11] = -m[0]*m[5]*m[11]  + m[0]*m[7]*m[9]   + m[4]*m[1]*m[11] - m[4]*m[3]*m[9]  - m[8]*m[1]*m[7]   + m[8]*m[3]*m[5];
        inv[15] =  m[0]*m[5]*m[10]  - m[0]*m[6]*m[9]   - m[4]*m[1]*m[10] + m[4]*m[2]*m[9]  + m[8]*m[1]*m[6]   - m[8]*m[2]*m[5];
        float det = m[0]*inv[0] + m[1]*inv[4] + m[2]*inv[8] + m[3]*inv[12];
        float rd = 1.0f / det;
        for (int n = 0; n < 16; n++) g_w2c[(tid - 64) * 16 + n] = inv[n] * rd;
    }
    for (int i = tid; i < 36864; i += blockDim.x) {
        int tap = i >> 12;
        int r = i & 4095;
        g_wT[i]         = w1[r * 9 + tap];
        g_wT[36864 + i] = w2[r * 9 + tap];
    }
}

__global__ void proj_kernel(const float* __restrict__ means,
                            const float* __restrict__ intrinsics) {
    int pi = blockIdx.y;
    int b = pi / 6, q = pi - b * 6;
    int j = c_pj[q], k = c_pk[q];
    int slot = (k < j) ? 0 : 1;
    int img = b * 4 + j;
    int pix = blockIdx.x * 256 + threadIdx.x;

    const float* m = means + ((long)img * HW + pix) * 3;
    float X = m[0], Y = m[1], Z = m[2];
    const float* w = g_w2c + (b * 4 + k) * 16;
    float c0 = w[0]*X + w[1]*Y + w[2]*Z  + w[3];
    float c1 = w[4]*X + w[5]*Y + w[6]*Z  + w[7];
    float c2 = w[8]*X + w[9]*Y + w[10]*Z + w[11];
    float dz = c2 + 1e-8f;
    float u0 = c0 / dz, u1 = c1 / dz, u2 = c2 / dz;
    const float* K = intrinsics + (b * 4 + k) * 9;
    float nx = K[0]*u0 + K[1]*u1 + K[2]*u2;
    float ny = K[3]*u0 + K[4]*u1 + K[5]*u2;
    bool mask = (nx >= 0.f) && (nx < 1.f) && (ny >= 0.f) && (ny < 1.f) && (c2 > 1e-8f);
    int px = (int)floorf(nx * 256.f);
    int py = (int)floorf(ny * 256.f);
    px = min(max(px, 0), 255);
    py = min(max(py, 0), 255);
    g_idx[(img * 2 + slot) * HW + pix] = mask ? (py * 256 + px) : -1;
    unsigned bal = __ballot_sync(0xFFFFFFFFu, mask);
    if ((threadIdx.x & 31) == 0)
        atomicAdd(&g_cnt[img * 2 + slot], __popc(bal));
}

__global__ void fuse_kernel(const float* __restrict__ feats) {
    const int img = blockIdx.y;
    const int j = img & 3;
    const int tid = threadIdx.x;
    const int pxl = tid & 63;
    const int chunk = tid >> 6;
    const int pix = (blockIdx.x << 6) + pxl;

    float s0 = 0.f, s1 = 0.f;
    int i0 = -1, i1 = -1;
    if (j > 0) {
        s0 = 0.1f * (float)g_cnt[img * 2 + 0] * (1.0f / 65536.f);
        i0 = g_idx[(img * 2 + 0) * HW + pix];
    }
    if (j < 3) {
        s1 = 0.1f * (float)g_cnt[img * 2 + 1] * (1.0f / 65536.f);
        i1 = g_idx[(img * 2 + 1) * HW + pix];
    }
    float rnorm = 1.f / (1.f + s0 + s1);

    const float4* sp = reinterpret_cast<const float4*>(feats + ((long)img * HW + pix) * 64 + (chunk << 4));
    float4 r[4];
#pragma unroll
    for (int q = 0; q < 4; q++) r[q] = sp[q];
    if (i0 >= 0) {
        const float4* gp = reinterpret_cast<const float4*>(feats + ((long)(img - 1) * HW + i0) * 64 + (chunk << 4));
#pragma unroll
        for (int q = 0; q < 4; q++) {
            float4 g = gp[q];
            r[q].x += s0 * g.x; r[q].y += s0 * g.y; r[q].z += s0 * g.z; r[q].w += s0 * g.w;
        }
    }
    if (i1 >= 0) {
        const float4* gp = reinterpret_cast<const float4*>(feats + ((long)(img + 1) * HW + i1) * 64 + (chunk << 4));
#pragma unroll
        for (int q = 0; q < 4; q++) {
            float4 g = gp[q];
            r[q].x += s1 * g.x; r[q].y += s1 * g.y; r[q].z += s1 * g.z; r[q].w += s1 * g.w;
        }
    }
    float* op = g_fused + ((long)img * 64 + (chunk << 4)) * HW + pix;
#pragma unroll
    for (int q = 0; q < 4; q++) {
        op[(q * 4 + 0) * HW] = r[q].x * rnorm;
        op[(q * 4 + 1) * HW] = r[q].y * rnorm;
        op[(q * 4 + 2) * HW] = r[q].z * rnorm;
        op[(q * 4 + 3) * HW] = r[q].w * rnorm;
    }
}

// 3x3 conv 64->64. dx outer (weight slab of 3 dy-taps in smem), inner loop
// loads bv[10] input rows once per ci-pair and reuses across the 3 dy taps.
// MODE0: g_fused -> gelu -> g_mid (NCHW). MODE1: g_mid -> out (NHWC).
template <int MODE>
__global__ __launch_bounds__(256, 2) void conv_kernel(const float* __restrict__ bias,
                                                      float* __restrict__ outp) {
    const float* __restrict__ in = (MODE == 0) ? g_fused : g_mid;
    const float* __restrict__ wT = g_wT + MODE * 36864;
    extern __shared__ float sm[];
    float* in_s = sm;            // [(yy*18+xx)*66 + ci], yy<10, xx<18
    float* w_s = sm + 11880;     // [dyl*4096 + co*64 + ci], 3 taps resident

    const int tid = threadIdx.x;
    const int x = tid & 15;
    const int cog = tid >> 4;
    const int img = blockIdx.z;
    const int y0 = blockIdx.y * 8;
    const int x0 = blockIdx.x * 16;

    const float* inb = in + (long)img * 64 * HW;
    for (int i = tid; i < 64 * 180; i += 256) {
        int ci = i / 180;
        int r = i - ci * 180;
        int yy = r / 18;
        int xx = r - yy * 18;
        int gy = y0 - 1 + yy, gx = x0 - 1 + xx;
        float v = 0.f;
        if ((unsigned)gy < 256u && (unsigned)gx < 256u)
            v = inb[ci * HW + (gy << 8) + gx];
        in_s[(yy * 18 + xx) * 66 + ci] = v;
    }

    unsigned long long acc[4][8];
#pragma unroll
    for (int p = 0; p < 4; p++)
#pragma unroll
        for (int k = 0; k < 8; k++) acc[p][k] = 0ull;

    for (int dx = 0; dx < 3; ++dx) {
        __syncthreads();
        // load weight slab: taps (dyl*3 + dx) for dyl = 0..2, as float4
        {
            const float4* src = reinterpret_cast<const float4*>(wT);
            float4* dst = reinterpret_cast<float4*>(w_s);
#pragma unroll
            for (int dyl = 0; dyl < 3; ++dyl) {
                const float4* s4 = src + (dyl * 3 + dx) * 1024;
                float4* d4 = dst + dyl * 1024;
                for (int i = tid; i < 1024; i += 256) d4[i] = s4[i];
            }
        }
        __syncthreads();

        const float* ircol = in_s + (x + dx) * 66;
        const float* wbase = w_s + cog * 4 * 64;
#pragma unroll 1
        for (int ci = 0; ci < 64; ci += 2) {
            unsigned long long bv[10];
#pragma unroll
            for (int r = 0; r < 10; r++) bv[r] = lds2(ircol + r * 1188 + ci);
#pragma unroll
            for (int dyl = 0; dyl < 3; ++dyl) {
                const float* wr = wbase + dyl * 4096 + ci;
                unsigned long long w0 = lds2(wr);
                unsigned long long w1v = lds2(wr + 64);
                unsigned long long w2v = lds2(wr + 128);
                unsigned long long w3v = lds2(wr + 192);
#pragma unroll
                for (int k = 0; k < 8; k++) {
                    acc[0][k] = fma2(w0, bv[k + dyl], acc[0][k]);
                    acc[1][k] = fma2(w1v, bv[k + dyl], acc[1][k]);
                    acc[2][k] = fma2(w2v, bv[k + dyl], acc[2][k]);
                    acc[3][k] = fma2(w3v, bv[k + dyl], acc[3][k]);
                }
            }
        }
    }

    if (MODE == 0) {
#pragma unroll
        for (int p = 0; p < 4; p++) {
            int co = cog * 4 + p;
            float bb = bias[co];
            float* ob = g_mid + ((long)img * 64 + co) * HW + (y0 << 8) + x0 + x;
#pragma unroll
            for (int k = 0; k < 8; k++) {
                float2 f = *reinterpret_cast<float2*>(&acc[p][k]);
                float v = f.x + f.y + bb;
                v = 0.5f * v * (1.0f + erff(v * 0.70710678118654752f));
                ob[k << 8] = v;
            }
        }
    } else {
        __syncthreads();
        float* st = sm; // [128 px][68]
#pragma unroll
        for (int p = 0; p < 4; p++) {
            int co = cog * 4 + p;
            float bb = bias[co];
#pragma unroll
            for (int k = 0; k < 8; k++) {
                float2 f = *reinterpret_cast<float2*>(&acc[p][k]);
                st[(k * 16 + x) * 68 + co] = f.x + f.y + bb;
            }
        }
        __syncthreads();
        const int lane = tid & 31, wrp = tid >> 5;
        for (int t = 0; t < 16; ++t) {
            int pxl = wrp * 16 + t;
            float2 v2 = *reinterpret_cast<float2*>(&st[pxl * 68 + lane * 2]);
            int py = pxl >> 4, pxx = pxl & 15;
            float* dst = outp + ((long)img * HW + ((y0 + py) << 8) + (x0 + pxx)) * 64 + lane * 2;
            *reinterpret_cast<float2*>(dst) = v2;
        }
    }
}

extern "C" void kernel_launch(void* const* d_in, const int* in_sizes, int n_in,
                              void* d_out, int out_size) {
    const float* means      = (const float*)d_in[0];
    const float* gs_feats   = (const float*)d_in[2];
    const float* intrinsics = (const float*)d_in[3];
    const float* extrinsics = (const float*)d_in[4];
    const float* w1 = (const float*)d_in[5];
    const float* b1 = (const float*)d_in[6];
    const float* w2 = (const float*)d_in[7];
    const float* b2 = (const float*)d_in[8];
    float* out = (float*)d_out;

    const int smem = (11880 + 12288) * 4;  // 96672 B
    cudaFuncSetAttribute(conv_kernel<0>, cudaFuncAttributeMaxDynamicSharedMemorySize, smem);
    cudaFuncSetAttribute(conv_kernel<1>, cudaFuncAttributeMaxDynamicSharedMemorySize, smem);

    setup_kernel<<<1, 256>>>(extrinsics, w1, w2);
    proj_kernel<<<dim3(256, 12), 256>>>(means, intrinsics);
    fuse_kernel<<<dim3(1024, 8), 256>>>(gs_feats);
    conv_kernel<0><<<dim3(16, 32, 8), 256, smem>>>(b1, out);
    conv_kernel<1><<<dim3(16, 32, 8), 256, smem>>>(b2, out);
}

// round 5
// speedup vs baseline: 1.6338x; 1.5859x over previous
#include <cuda_runtime.h>
#include <math.h>
#include <stdint.h>

#define HW 65536

// ---------------- device scratch ----------------
__device__ float g_w2c[8 * 16];
__device__ int   g_idx[16 * HW];
__device__ int   g_cnt[16];
__device__ float g_wB[2 * 9 * 64 * 64];   // [conv][tap][co][ci], tf32-rounded
__device__ float g_fused[8ll * HW * 64];  // NHWC
__device__ float g_mid[8ll * HW * 64];    // NHWC

__constant__ int c_pj[6] = {0, 1, 1, 2, 2, 3};
__constant__ int c_pk[6] = {1, 0, 2, 1, 3, 2};

__device__ __forceinline__ float rtf32(float x) {
    uint32_t u;
    asm("cvt.rna.tf32.f32 %0, %1;" : "=r"(u) : "f"(x));
    return __uint_as_float(u);
}
__device__ __forceinline__ uint32_t smem_u32(const void* p) {
    uint32_t a;
    asm("{ .reg .u64 t; cvta.to.shared.u64 t, %1; cvt.u32.u64 %0, t; }" : "=r"(a) : "l"(p));
    return a;
}
__device__ __forceinline__ void mma_tf32(float* d, const uint32_t* a, const uint32_t* b) {
    asm volatile(
        "mma.sync.aligned.m16n8k8.row.col.f32.tf32.tf32.f32 "
        "{%0,%1,%2,%3}, {%4,%5,%6,%7}, {%8,%9}, {%0,%1,%2,%3};"
        : "+f"(d[0]), "+f"(d[1]), "+f"(d[2]), "+f"(d[3])
        : "r"(a[0]), "r"(a[1]), "r"(a[2]), "r"(a[3]), "r"(b[0]), "r"(b[1]));
}

// ---------------- setup ----------------
__global__ void setup_kernel(const float* __restrict__ extr,
                             const float* __restrict__ w1,
                             const float* __restrict__ w2) {
    int tid = threadIdx.x;
    if (tid < 16) g_cnt[tid] = 0;
    if (tid >= 64 && tid < 72) {
        const float* m = extr + (tid - 64) * 16;
        float inv[16];
        inv[0]  =  m[5]*m[10]*m[15] - m[5]*m[11]*m[14] - m[9]*m[6]*m[15] + m[9]*m[7]*m[14] + m[13]*m[6]*m[11] - m[13]*m[7]*m[10];
        inv[4]  = -m[4]*m[10]*m[15] + m[4]*m[11]*m[14] + m[8]*m[6]*m[15] - m[8]*m[7]*m[14] - m[12]*m[6]*m[11] + m[12]*m[7]*m[10];
        inv[8]  =  m[4]*m[9]*m[15]  - m[4]*m[11]*m[13] - m[8]*m[5]*m[15] + m[8]*m[7]*m[13] + m[12]*m[5]*m[11] - m[12]*m[7]*m[9];
        inv[12] = -m[4]*m[9]*m[14]  + m[4]*m[10]*m[13] + m[8]*m[5]*m[14] - m[8]*m[6]*m[13] - m[12]*m[5]*m[10] + m[12]*m[6]*m[9];
        inv[1]  = -m[1]*m[10]*m[15] + m[1]*m[11]*m[14] + m[9]*m[2]*m[15] - m[9]*m[3]*m[14] - m[13]*m[2]*m[11] + m[13]*m[3]*m[10];
        inv[5]  =  m[0]*m[10]*m[15] - m[0]*m[11]*m[14] - m[8]*m[2]*m[15] + m[8]*m[3]*m[14] + m[12]*m[2]*m[11] - m[12]*m[3]*m[10];
        inv[9]  = -m[0]*m[9]*m[15]  + m[0]*m[11]*m[13] + m[8]*m[1]*m[15] - m[8]*m[3]*m[13] - m[12]*m[1]*m[11] + m[12]*m[3]*m[9];
        inv[13] =  m[0]*m[9]*m[14]  - m[0]*m[10]*m[13] - m[8]*m[1]*m[14] + m[8]*m[2]*m[13] + m[12]*m[1]*m[10] - m[12]*m[2]*m[9];
        inv[2]  =  m[1]*m[6]*m[15]  - m[1]*m[7]*m[14]  - m[5]*m[2]*m[15] + m[5]*m[3]*m[14] + m[13]*m[2]*m[7]  - m[13]*m[3]*m[6];
        inv[6]  = -m[0]*m[6]*m[15]  + m[0]*m[7]*m[14]  + m[4]*m[2]*m[15] - m[4]*m[3]*m[14] - m[12]*m[2]*m[7]  + m[12]*m[3]*m[6];
        inv[10] =  m[0]*m[5]*m[15]  - m[0]*m[7]*m[13]  - m[4]*m[1]*m[15] + m[4]*m[3]*m[13] + m[12]*m[1]*m[7]  - m[12]*m[3]*m[5];
        inv[14] = -m[0]*m[5]*m[14]  + m[0]*m[6]*m[13]  + m[4]*m[1]*m[14] - m[4]*m[2]*m[13] - m[12]*m[1]*m[6]  + m[12]*m[2]*m[5];
        inv[3]  = -m[1]*m[6]*m[11]  + m[1]*m[7]*m[10]  + m[5]*m[2]*m[11] - m[5]*m[3]*m[10] - m[9]*m[2]*m[7]   + m[9]*m[3]*m[6];
        inv[7]  =  m[0]*m[6]*m[11]  - m[0]*m[7]*m[10]  - m[4]*m[2]*m[11] + m[4]*m[3]*m[10] + m[8]*m[2]*m[7]   - m[8]*m[3]*m[6];
        inv[11] = -m[0]*m[5]*m[11]  + m[0]*m[7]*m[9]   + m[4]*m[1]*m[11] - m[4]*m[3]*m[9]  - m[8]*m[1]*m[7]   + m[8]*m[3]*m[5];
        inv[15] =  m[0]*m[5]*m[10]  - m[0]*m[6]*m[9]   - m[4]*m[1]*m[10] + m[4]*m[2]*m[9]  + m[8]*m[1]*m[6]   - m[8]*m[2]*m[5];
        float det = m[0]*inv[0] + m[1]*inv[4] + m[2]*inv[8] + m[3]*inv[12];
        float rd = 1.0f / det;
        for (int n = 0; n < 16; n++) g_w2c[(tid - 64) * 16 + n] = inv[n] * rd;
    }
    for (int i = tid; i < 73728; i += blockDim.x) {
        int c = i / 36864;
        int r = i - c * 36864;
        int tap = r >> 12;
        int q = r & 4095;
        int co = q >> 6, ci = q & 63;
        g_wB[i] = rtf32((c ? w2 : w1)[(co * 64 + ci) * 9 + tap]);
    }
}

// ---------------- phase 1: projection + mask counts ----------------
__global__ void proj_kernel(const float* __restrict__ means,
                            const float* __restrict__ intrinsics) {
    int pi = blockIdx.y;
    int b = pi / 6, q = pi - b * 6;
    int j = c_pj[q], k = c_pk[q];
    int slot = (k < j) ? 0 : 1;
    int img = b * 4 + j;
    int pix = blockIdx.x * 256 + threadIdx.x;

    const float* m = means + ((long)img * HW + pix) * 3;
    float X = m[0], Y = m[1], Z = m[2];
    const float* w = g_w2c + (b * 4 + k) * 16;
    float c0 = w[0]*X + w[1]*Y + w[2]*Z  + w[3];
    float c1 = w[4]*X + w[5]*Y + w[6]*Z  + w[7];
    float c2 = w[8]*X + w[9]*Y + w[10]*Z + w[11];
    float dz = c2 + 1e-8f;
    float u0 = c0 / dz, u1 = c1 / dz, u2 = c2 / dz;
    const float* K = intrinsics + (b * 4 + k) * 9;
    float nx = K[0]*u0 + K[1]*u1 + K[2]*u2;
    float ny = K[3]*u0 + K[4]*u1 + K[5]*u2;
    bool mask = (nx >= 0.f) && (nx < 1.f) && (ny >= 0.f) && (ny < 1.f) && (c2 > 1e-8f);
    int px = (int)floorf(nx * 256.f);
    int py = (int)floorf(ny * 256.f);
    px = min(max(px, 0), 255);
    py = min(max(py, 0), 255);
    g_idx[(img * 2 + slot) * HW + pix] = mask ? (py * 256 + px) : -1;
    unsigned bal = __ballot_sync(0xFFFFFFFFu, mask);
    if ((threadIdx.x & 31) == 0)
        atomicAdd(&g_cnt[img * 2 + slot], __popc(bal));
}

// ---------------- phase 2: weighted fusion -> NHWC (tf32-rounded) ----------
__global__ void fuse_kernel(const float* __restrict__ feats) {
    const int img = blockIdx.y;
    const int j = img & 3;
    const int tid = threadIdx.x;
    const int pxl = tid & 63;
    const int chunk = tid >> 6;
    const int pix = (blockIdx.x << 6) + pxl;

    float s0 = 0.f, s1 = 0.f;
    int i0 = -1, i1 = -1;
    if (j > 0) {
        s0 = 0.1f * (float)g_cnt[img * 2 + 0] * (1.0f / 65536.f);
        i0 = g_idx[(img * 2 + 0) * HW + pix];
    }
    if (j < 3) {
        s1 = 0.1f * (float)g_cnt[img * 2 + 1] * (1.0f / 65536.f);
        i1 = g_idx[(img * 2 + 1) * HW + pix];
    }
    float rnorm = 1.f / (1.f + s0 + s1);

    const float4* sp = reinterpret_cast<const float4*>(feats + ((long)img * HW + pix) * 64 + (chunk << 4));
    float4 r[4];
#pragma unroll
    for (int q = 0; q < 4; q++) r[q] = sp[q];
    if (i0 >= 0) {
        const float4* gp = reinterpret_cast<const float4*>(feats + ((long)(img - 1) * HW + i0) * 64 + (chunk << 4));
#pragma unroll
        for (int q = 0; q < 4; q++) {
            float4 g = gp[q];
            r[q].x += s0 * g.x; r[q].y += s0 * g.y; r[q].z += s0 * g.z; r[q].w += s0 * g.w;
        }
    }
    if (i1 >= 0) {
        const float4* gp = reinterpret_cast<const float4*>(feats + ((long)(img + 1) * HW + i1) * 64 + (chunk << 4));
#pragma unroll
        for (int q = 0; q < 4; q++) {
            float4 g = gp[q];
            r[q].x += s1 * g.x; r[q].y += s1 * g.y; r[q].z += s1 * g.z; r[q].w += s1 * g.w;
        }
    }
    float4* op = reinterpret_cast<float4*>(g_fused + ((long)img * HW + pix) * 64 + (chunk << 4));
#pragma unroll
    for (int q = 0; q < 4; q++) {
        float4 v;
        v.x = rtf32(r[q].x * rnorm);
        v.y = rtf32(r[q].y * rnorm);
        v.z = rtf32(r[q].z * rnorm);
        v.w = rtf32(r[q].w * rnorm);
        op[q] = v;
    }
}

// ---------------- conv via mma.sync tf32 implicit GEMM ----------------
// Tile: 128 px x 64 co; 8 warps = (4 px-groups of 32px) x (2 co-groups of 32co).
// Weights resident in smem all 9 taps; X double-buffered per tap via cp.async.
// smem (floats): W 9*64*68=39168 | X 2*128*68=17408 | bias 64  -> 226,560 B
template <int MODE>
__global__ __launch_bounds__(256, 1) void conv_mma(const float* __restrict__ bias,
                                                   float* __restrict__ d_outp) {
    extern __shared__ float sm[];
    float* Wsm = sm;
    float* Xsm = sm + 39168;
    float* bsm = sm + 39168 + 17408;
    const int tid = threadIdx.x;
    const float* __restrict__ inp = (MODE == 0) ? g_fused : g_mid;
    float* __restrict__ outp = (MODE == 0) ? g_mid : d_outp;

    for (int i = tid; i < 36864; i += 256) {
        int tap = i >> 12, q = i & 4095;
        Wsm[tap * 4352 + (q >> 6) * 68 + (q & 63)] = g_wB[MODE * 36864 + i];
    }
    if (tid < 64) bsm[tid] = bias[tid];
    __syncthreads();

    const uint32_t Xb = smem_u32(Xsm);
    const int lane = tid & 31, wrp = tid >> 5;
    const int grp = lane >> 2, q4 = lane & 3;
    const int pxq = wrp & 3, coq = wrp >> 2;
    const int ldpx = tid >> 1, ldh = tid & 1;

    for (int tile = blockIdx.x; tile < 4096; tile += gridDim.x) {
        const int img = tile >> 9;
        const int rem = tile & 511;
        const int y = rem >> 1;
        const int x0 = (rem & 1) << 7;

        float d[2][4][4];
#pragma unroll
        for (int m = 0; m < 2; m++)
#pragma unroll
            for (int n = 0; n < 4; n++)
#pragma unroll
                for (int e = 0; e < 4; e++) d[m][n][e] = 0.f;

        // prologue: issue tap 0 into buf 0
        {
            const int gy = y - 1, gx = x0 + ldpx - 1;
            const int ok = ((unsigned)gy < 256u && (unsigned)gx < 256u) ? 16 : 0;
            const int cy = min(max(gy, 0), 255), cx = min(max(gx, 0), 255);
            const char* src = (const char*)(inp + (((long)img * 256 + cy) * 256 + cx) * 64 + ldh * 32);
            uint32_t dst = Xb + (uint32_t)(ldpx * 68 + ldh * 32) * 4u;
#pragma unroll
            for (int i = 0; i < 8; i++)
                asm volatile("cp.async.cg.shared.global [%0], [%1], 16, %2;"
                             :: "r"(dst + i * 16), "l"(src + i * 16), "r"(ok));
            asm volatile("cp.async.commit_group;" ::: "memory");
        }

        for (int tap = 0; tap < 9; ++tap) {
            if (tap < 8) {
                const int t = tap + 1;
                const int dy = t / 3 - 1, dxm = t - (t / 3) * 3 - 1;
                const int gy = y + dy, gx = x0 + ldpx + dxm;
                const int ok = ((unsigned)gy < 256u && (unsigned)gx < 256u) ? 16 : 0;
                const int cy = min(max(gy, 0), 255), cx = min(max(gx, 0), 255);
                const char* src = (const char*)(inp + (((long)img * 256 + cy) * 256 + cx) * 64 + ldh * 32);
                uint32_t dst = Xb + (uint32_t)((t & 1) * 8704 + ldpx * 68 + ldh * 32) * 4u;
#pragma unroll
                for (int i = 0; i < 8; i++)
                    asm volatile("cp.async.cg.shared.global [%0], [%1], 16, %2;"
                                 :: "r"(dst + i * 16), "l"(src + i * 16), "r"(ok));
                asm volatile("cp.async.commit_group;" ::: "memory");
                asm volatile("cp.async.wait_group 1;" ::: "memory");
            } else {
                asm volatile("cp.async.wait_group 0;" ::: "memory");
            }
            __syncthreads();

            const float* X = Xsm + (tap & 1) * 8704;
            const float* W = Wsm + tap * 4352;
            const float* xr0 = X + (pxq * 32 + grp) * 68 + q4;
            const float* wr0 = W + (coq * 32 + grp) * 68 + q4;
#pragma unroll
            for (int k8 = 0; k8 < 8; ++k8) {
                const int kc = k8 * 8;
                uint32_t a[2][4], b[4][2];
#pragma unroll
                for (int m = 0; m < 2; m++) {
                    const float* p = xr0 + m * 16 * 68 + kc;
                    a[m][0] = __float_as_uint(p[0]);
                    a[m][1] = __float_as_uint(p[8 * 68]);
                    a[m][2] = __float_as_uint(p[4]);
                    a[m][3] = __float_as_uint(p[8 * 68 + 4]);
                }
#pragma unroll
                for (int n = 0; n < 4; n++) {
                    const float* p = wr0 + n * 8 * 68 + kc;
                    b[n][0] = __float_as_uint(p[0]);
                    b[n][1] = __float_as_uint(p[4]);
                }
#pragma unroll
                for (int m = 0; m < 2; m++)
#pragma unroll
                    for (int n = 0; n < 4; n++) mma_tf32(d[m][n], a[m], b[n]);
            }
            __syncthreads();
        }

        // epilogue
#pragma unroll
        for (int m = 0; m < 2; m++) {
#pragma unroll
            for (int half = 0; half < 2; half++) {
                const int px = pxq * 32 + m * 16 + grp + half * 8;
                float* o = outp + (((long)img * 256 + y) * 256 + x0 + px) * 64;
#pragma unroll
                for (int n = 0; n < 4; n++) {
                    const int co = coq * 32 + n * 8 + q4 * 2;
                    float2 v;
                    v.x = d[m][n][half * 2 + 0] + bsm[co];
                    v.y = d[m][n][half * 2 + 1] + bsm[co + 1];
                    if (MODE == 0) {
                        v.x = rtf32(0.5f * v.x * (1.0f + erff(v.x * 0.70710678118654752f)));
                        v.y = rtf32(0.5f * v.y * (1.0f + erff(v.y * 0.70710678118654752f)));
                    }
                    *reinterpret_cast<float2*>(o + co) = v;
                }
            }
        }
    }
}

// ---------------- launch ----------------
extern "C" void kernel_launch(void* const* d_in, const int* in_sizes, int n_in,
                              void* d_out, int out_size) {
    const float* means      = (const float*)d_in[0];
    const float* gs_feats   = (const float*)d_in[2];
    const float* intrinsics = (const float*)d_in[3];
    const float* extrinsics = (const float*)d_in[4];
    const float* w1 = (const float*)d_in[5];
    const float* b1 = (const float*)d_in[6];
    const float* w2 = (const float*)d_in[7];
    const float* b2 = (const float*)d_in[8];
    float* out = (float*)d_out;

    const int smem = (39168 + 17408 + 64) * 4;  // 226,560 B
    cudaFuncSetAttribute(conv_mma<0>, cudaFuncAttributeMaxDynamicSharedMemorySize, smem);
    cudaFuncSetAttribute(conv_mma<1>, cudaFuncAttributeMaxDynamicSharedMemorySize, smem);

    setup_kernel<<<1, 256>>>(extrinsics, w1, w2);
    proj_kernel<<<dim3(256, 12), 256>>>(means, intrinsics);
    fuse_kernel<<<dim3(1024, 8), 256>>>(gs_feats);
    conv_mma<0><<<148, 256, smem>>>(b1, out);
    conv_mma<1><<<148, 256, smem>>>(b2, out);
}

// round 6
// speedup vs baseline: 3.3030x; 2.0217x over previous
#include <cuda_runtime.h>
#include <math.h>
#include <stdint.h>

#define HW 65536

// ---------------- device scratch ----------------
__device__ float g_w2c[8 * 16];
__device__ int   g_idx[16 * HW];
__device__ int   g_cnt[16];
__device__ float g_wB[2 * 2 * 9 * 32 * 64]; // [conv][coh][tap][co32][64] swizzled+paired
__device__ float g_fused[8ll * HW * 64];    // NHWC tf32
__device__ float g_mid[8ll * HW * 64];      // NHWC tf32

__constant__ int c_pj[6] = {0, 1, 1, 2, 2, 3};
__constant__ int c_pk[6] = {1, 0, 2, 1, 3, 2};

__device__ __forceinline__ float rtf32(float x) {
    uint32_t u;
    asm("cvt.rna.tf32.f32 %0, %1;" : "=r"(u) : "f"(x));
    return __uint_as_float(u);
}
__device__ __forceinline__ uint32_t smem_u32(const void* p) {
    uint32_t a;
    asm("{ .reg .u64 t; cvta.to.shared.u64 t, %1; cvt.u32.u64 %0, t; }" : "=r"(a) : "l"(p));
    return a;
}
__device__ __forceinline__ void mma_tf32(float* d, const uint32_t* a, const uint32_t* b) {
    asm volatile(
        "mma.sync.aligned.m16n8k8.row.col.f32.tf32.tf32.f32 "
        "{%0,%1,%2,%3}, {%4,%5,%6,%7}, {%8,%9}, {%0,%1,%2,%3};"
        : "+f"(d[0]), "+f"(d[1]), "+f"(d[2]), "+f"(d[3])
        : "r"(a[0]), "r"(a[1]), "r"(a[2]), "r"(a[3]), "r"(b[0]), "r"(b[1]));
}

// ---------------- setup ----------------
__global__ void setup_kernel(const float* __restrict__ extr,
                             const float* __restrict__ w1,
                             const float* __restrict__ w2) {
    int tid = threadIdx.x;
    if (tid < 16) g_cnt[tid] = 0;
    if (tid >= 64 && tid < 72) {
        const float* m = extr + (tid - 64) * 16;
        float inv[16];
        inv[0]  =  m[5]*m[10]*m[15] - m[5]*m[11]*m[14] - m[9]*m[6]*m[15] + m[9]*m[7]*m[14] + m[13]*m[6]*m[11] - m[13]*m[7]*m[10];
        inv[4]  = -m[4]*m[10]*m[15] + m[4]*m[11]*m[14] + m[8]*m[6]*m[15] - m[8]*m[7]*m[14] - m[12]*m[6]*m[11] + m[12]*m[7]*m[10];
        inv[8]  =  m[4]*m[9]*m[15]  - m[4]*m[11]*m[13] - m[8]*m[5]*m[15] + m[8]*m[7]*m[13] + m[12]*m[5]*m[11] - m[12]*m[7]*m[9];
        inv[12] = -m[4]*m[9]*m[14]  + m[4]*m[10]*m[13] + m[8]*m[5]*m[14] - m[8]*m[6]*m[13] - m[12]*m[5]*m[10] + m[12]*m[6]*m[9];
        inv[1]  = -m[1]*m[10]*m[15] + m[1]*m[11]*m[14] + m[9]*m[2]*m[15] - m[9]*m[3]*m[14] - m[13]*m[2]*m[11] + m[13]*m[3]*m[10];
        inv[5]  =  m[0]*m[10]*m[15] - m[0]*m[11]*m[14] - m[8]*m[2]*m[15] + m[8]*m[3]*m[14] + m[12]*m[2]*m[11] - m[12]*m[3]*m[10];
        inv[9]  = -m[0]*m[9]*m[15]  + m[0]*m[11]*m[13] + m[8]*m[1]*m[15] - m[8]*m[3]*m[13] - m[12]*m[1]*m[11] + m[12]*m[3]*m[9];
        inv[13] =  m[0]*m[9]*m[14]  - m[0]*m[10]*m[13] - m[8]*m[1]*m[14] + m[8]*m[2]*m[13] + m[12]*m[1]*m[10] - m[12]*m[2]*m[9];
        inv[2]  =  m[1]*m[6]*m[15]  - m[1]*m[7]*m[14]  - m[5]*m[2]*m[15] + m[5]*m[3]*m[14] + m[13]*m[2]*m[7]  - m[13]*m[3]*m[6];
        inv[6]  = -m[0]*m[6]*m[15]  + m[0]*m[7]*m[14]  + m[4]*m[2]*m[15] - m[4]*m[3]*m[14] - m[12]*m[2]*m[7]  + m[12]*m[3]*m[6];
        inv[10] =  m[0]*m[5]*m[15]  - m[0]*m[7]*m[13]  - m[4]*m[1]*m[15] + m[4]*m[3]*m[13] + m[12]*m[1]*m[7]  - m[12]*m[3]*m[5];
        inv[14] = -m[0]*m[5]*m[14]  + m[0]*m[6]*m[13]  + m[4]*m[1]*m[14] - m[4]*m[2]*m[13] - m[12]*m[1]*m[6]  + m[12]*m[2]*m[5];
        inv[3]  = -m[1]*m[6]*m[11]  + m[1]*m[7]*m[10]  + m[5]*m[2]*m[11] - m[5]*m[3]*m[10] - m[9]*m[2]*m[7]   + m[9]*m[3]*m[6];
        inv[7]  =  m[0]*m[6]*m[11]  - m[0]*m[7]*m[10]  - m[4]*m[2]*m[11] + m[4]*m[3]*m[10] + m[8]*m[2]*m[7]   - m[8]*m[3]*m[6];
        inv[11] = -m[0]*m[5]*m[11]  + m[0]*m[7]*m[9]   + m[4]*m[1]*m[11] - m[4]*m[3]*m[9]  - m[8]*m[1]*m[7]   + m[8]*m[3]*m[5];
        inv[15] =  m[0]*m[5]*m[10]  - m[0]*m[6]*m[9]   - m[4]*m[1]*m[10] + m[4]*m[2]*m[9]  + m[8]*m[1]*m[6]   - m[8]*m[2]*m[5];
        float det = m[0]*inv[0] + m[1]*inv[4] + m[2]*inv[8] + m[3]*inv[12];
        float rd = 1.0f / det;
        for (int n = 0; n < 16; n++) g_w2c[(tid - 64) * 16 + n] = inv[n] * rd;
    }
    // W layout: [conv][coh][tap][col 0..31][pofs], paired (ci, ci+4) + XOR swizzle
    for (int i = tid; i < 73728; i += blockDim.x) {
        int c = i / 36864;
        int r = i - c * 36864;
        int tap = r >> 12;
        int q = r & 4095;
        int co = q >> 6, ci = q & 63;
        int coh = co >> 5, col = co & 31;
        int k8 = ci >> 3, q4r = ci & 3, e = (ci >> 2) & 1;
        int pofs = (((k8 * 4 + q4r) ^ ((col & 7) * 4)) << 1) + e;
        int dst = ((c * 2 + coh) * 9 + tap) * 2048 + col * 64 + pofs;
        g_wB[dst] = rtf32((c ? w2 : w1)[(co * 64 + ci) * 9 + tap]);
    }
}

// ---------------- phase 1: projection + mask counts ----------------
__global__ void proj_kernel(const float* __restrict__ means,
                            const float* __restrict__ intrinsics) {
    int pi = blockIdx.y;
    int b = pi / 6, q = pi - b * 6;
    int j = c_pj[q], k = c_pk[q];
    int slot = (k < j) ? 0 : 1;
    int img = b * 4 + j;
    int pix = blockIdx.x * 256 + threadIdx.x;

    const float* m = means + ((long)img * HW + pix) * 3;
    float X = m[0], Y = m[1], Z = m[2];
    const float* w = g_w2c + (b * 4 + k) * 16;
    float c0 = w[0]*X + w[1]*Y + w[2]*Z  + w[3];
    float c1 = w[4]*X + w[5]*Y + w[6]*Z  + w[7];
    float c2 = w[8]*X + w[9]*Y + w[10]*Z + w[11];
    float dz = c2 + 1e-8f;
    float u0 = c0 / dz, u1 = c1 / dz, u2 = c2 / dz;
    const float* K = intrinsics + (b * 4 + k) * 9;
    float nx = K[0]*u0 + K[1]*u1 + K[2]*u2;
    float ny = K[3]*u0 + K[4]*u1 + K[5]*u2;
    bool mask = (nx >= 0.f) && (nx < 1.f) && (ny >= 0.f) && (ny < 1.f) && (c2 > 1e-8f);
    int px = (int)floorf(nx * 256.f);
    int py = (int)floorf(ny * 256.f);
    px = min(max(px, 0), 255);
    py = min(max(py, 0), 255);
    g_idx[(img * 2 + slot) * HW + pix] = mask ? (py * 256 + px) : -1;
    unsigned bal = __ballot_sync(0xFFFFFFFFu, mask);
    if ((threadIdx.x & 31) == 0)
        atomicAdd(&g_cnt[img * 2 + slot], __popc(bal));
}

// ---------------- phase 2: weighted fusion -> NHWC (tf32-rounded) ----------
__global__ void fuse_kernel(const float* __restrict__ feats) {
    const int img = blockIdx.y;
    const int j = img & 3;
    const int tid = threadIdx.x;
    const int pxl = tid & 63;
    const int chunk = tid >> 6;
    const int pix = (blockIdx.x << 6) + pxl;

    float s0 = 0.f, s1 = 0.f;
    int i0 = -1, i1 = -1;
    if (j > 0) {
        s0 = 0.1f * (float)g_cnt[img * 2 + 0] * (1.0f / 65536.f);
        i0 = g_idx[(img * 2 + 0) * HW + pix];
    }
    if (j < 3) {
        s1 = 0.1f * (float)g_cnt[img * 2 + 1] * (1.0f / 65536.f);
        i1 = g_idx[(img * 2 + 1) * HW + pix];
    }
    float rnorm = 1.f / (1.f + s0 + s1);

    const float4* sp = reinterpret_cast<const float4*>(feats + ((long)img * HW + pix) * 64 + (chunk << 4));
    float4 r[4];
#pragma unroll
    for (int q = 0; q < 4; q++) r[q] = sp[q];
    if (i0 >= 0) {
        const float4* gp = reinterpret_cast<const float4*>(feats + ((long)(img - 1) * HW + i0) * 64 + (chunk << 4));
#pragma unroll
        for (int q = 0; q < 4; q++) {
            float4 g = gp[q];
            r[q].x += s0 * g.x; r[q].y += s0 * g.y; r[q].z += s0 * g.z; r[q].w += s0 * g.w;
        }
    }
    if (i1 >= 0) {
        const float4* gp = reinterpret_cast<const float4*>(feats + ((long)(img + 1) * HW + i1) * 64 + (chunk << 4));
#pragma unroll
        for (int q = 0; q < 4; q++) {
            float4 g = gp[q];
            r[q].x += s1 * g.x; r[q].y += s1 * g.y; r[q].z += s1 * g.z; r[q].w += s1 * g.w;
        }
    }
    float4* op = reinterpret_cast<float4*>(g_fused + ((long)img * HW + pix) * 64 + (chunk << 4));
#pragma unroll
    for (int q = 0; q < 4; q++) {
        float4 v;
        v.x = rtf32(r[q].x * rnorm);
        v.y = rtf32(r[q].y * rnorm);
        v.z = rtf32(r[q].z * rnorm);
        v.w = rtf32(r[q].w * rnorm);
        op[q] = v;
    }
}

// ---------------- conv: tf32 mma, input-row walk ----------------
// CTA = (img, co-half, y-seg). Walk input rows y0-1 .. y0+rows; each row strip
// (258 px x 64 ci) loaded once, contributes 3 dy taps to 3 register acc slots.
// smem: W 73728 B | X 2x66048 B | bias 128 B = 205,952 B.
#define GELU(v) (0.5f * (v) * (1.0f + erff((v) * 0.70710678118654752f)))

#define CONV_BODY(PH, STEPV) do {                                              \
    const int step_ = (STEPV);                                                 \
    { /* prefetch input row r+1 = y0+step_ into slot (step_+1)&1 */            \
        int rn = y0 + step_;                                                   \
        int okr = (rn < 256) ? 1 : 0;                                          \
        const char* rowp = (const char*)(inp + ((long)img * 256 + min(rn, 255)) * 16384); \
        uint32_t dstb = Xb + (uint32_t)(((step_ + 1) & 1) * 66048);            \
        for (int i = tid; i < 4128; i += 256) {                                \
            int p = i >> 4, c = i & 15;                                        \
            int gx = p - 1;                                                    \
            int ok = (okr && (unsigned)gx < 256u) ? 16 : 0;                    \
            const char* src = rowp + (uint32_t)min(max(gx, 0), 255) * 256u + (uint32_t)c * 16u; \
            uint32_t dst = dstb + (uint32_t)p * 256u + (uint32_t)((c ^ (p & 7)) << 4); \
            asm volatile("cp.async.cg.shared.global [%0], [%1], 16, %2;"       \
                         :: "r"(dst), "l"(src), "r"(ok));                      \
        }                                                                      \
        asm volatile("cp.async.commit_group;" ::: "memory");                   \
    }                                                                          \
    asm volatile("cp.async.wait_group 1;" ::: "memory");                       \
    __syncthreads();                                                           \
    {                                                                          \
        const float* X = Xf + (step_ & 1) * 16512;                             \
        _Pragma("unroll")                                                      \
        for (int k8 = 0; k8 < 8; k8++) {                                       \
            const int kc = k8 * 8;                                             \
            uint32_t a[3][2][4];                                               \
            _Pragma("unroll")                                                  \
            for (int dxm = 0; dxm < 3; dxm++) {                                \
                const int aswz = ((grp + dxm) & 7) * 4;                        \
                const int c0 = (kc + q4) ^ aswz, c1 = (kc + q4 + 4) ^ aswz;    \
                _Pragma("unroll")                                              \
                for (int mt = 0; mt < 2; mt++) {                               \
                    const float* xp = X + (pb + mt * 16 + grp + dxm) * 64;     \
                    a[dxm][mt][0] = __float_as_uint(xp[c0]);                   \
                    a[dxm][mt][1] = __float_as_uint(xp[512 + c0]);             \
                    a[dxm][mt][2] = __float_as_uint(xp[c1]);                   \
                    a[dxm][mt][3] = __float_as_uint(xp[512 + c1]);             \
                }                                                              \
            }                                                                  \
            _Pragma("unroll")                                                  \
            for (int tr = 0; tr < 3; tr++) {                                   \
                const int S = ((PH) + 1 - tr + 3) % 3;                         \
                if (tr == 0 || step_ >= tr) {                                  \
                    _Pragma("unroll")                                          \
                    for (int dxm = 0; dxm < 3; dxm++) {                        \
                        const int tap = tr * 3 + dxm;                          \
                        const float2* wp = (const float2*)(Wf + tap * 2048);   \
                        const int pofs = (k8 * 4 + q4) ^ (grp * 4);            \
                        uint32_t bb[4][2];                                     \
                        _Pragma("unroll")                                      \
                        for (int n = 0; n < 4; n++) {                          \
                            float2 t = wp[(n * 8 + grp) * 32 + pofs];          \
                            bb[n][0] = __float_as_uint(t.x);                   \
                            bb[n][1] = __float_as_uint(t.y);                   \
                        }                                                      \
                        _Pragma("unroll")                                      \
                        for (int mt = 0; mt < 2; mt++)                         \
                            _Pragma("unroll")                                  \
                            for (int n = 0; n < 4; n++)                        \
                                mma_tf32(acc[S][mt][n], a[dxm][mt], bb[n]);    \
                    }                                                          \
                }                                                              \
            }                                                                  \
        }                                                                      \
    }                                                                          \
    if (step_ >= 2) {                                                          \
        const int E = ((PH) + 2) % 3;                                          \
        const int o = y0 + step_ - 2;                                          \
        _Pragma("unroll")                                                      \
        for (int mt = 0; mt < 2; mt++) {                                       \
            _Pragma("unroll")                                                  \
            for (int h = 0; h < 2; h++) {                                      \
                const int px = pb + mt * 16 + grp + h * 8;                     \
                float* op = outp + (((long)img * 256 + o) * 256 + px) * 64 + coh * 32; \
                _Pragma("unroll")                                              \
                for (int n = 0; n < 4; n++) {                                  \
                    const int co = n * 8 + q4 * 2;                             \
                    float2 v;                                                  \
                    v.x = acc[E][mt][n][h * 2 + 0] + bsm[co];                  \
                    v.y = acc[E][mt][n][h * 2 + 1] + bsm[co + 1];              \
                    if (MODE == 0) {                                           \
                        v.x = rtf32(GELU(v.x));                                \
                        v.y = rtf32(GELU(v.y));                                \
                    }                                                          \
                    *reinterpret_cast<float2*>(op + co) = v;                   \
                }                                                              \
            }                                                                  \
        }                                                                      \
        _Pragma("unroll")                                                      \
        for (int mt = 0; mt < 2; mt++)                                         \
            _Pragma("unroll")                                                  \
            for (int n = 0; n < 4; n++)                                        \
                _Pragma("unroll")                                              \
                for (int e = 0; e < 4; e++) acc[E][mt][n][e] = 0.f;            \
    }                                                                          \
    __syncthreads();                                                           \
} while (0)

template <int MODE>
__global__ __launch_bounds__(256, 1) void conv_mma(const float* __restrict__ bias,
                                                   float* __restrict__ d_outp) {
    extern __shared__ float sm[];
    float* Wf = sm;                    // 18432 floats
    float* Xf = sm + 18432;            // 2 x 16512 floats
    float* bsm = sm + 18432 + 33024;   // 32 floats

    const int tid = threadIdx.x;
    const int bx = blockIdx.x;
    const int img = bx / 18;
    const int coh = (bx / 9) & 1;
    const int seg = bx % 9;
    const int y0 = seg * 29;
    const int rows = (seg == 8) ? 24 : 29;

    const float* __restrict__ inp = (MODE == 0) ? g_fused : g_mid;
    float* __restrict__ outp = (MODE == 0) ? g_mid : d_outp;

    {
        const float4* ws = reinterpret_cast<const float4*>(g_wB + (MODE * 2 + coh) * 18432);
        float4* wd = reinterpret_cast<float4*>(Wf);
        for (int i = tid; i < 4608; i += 256) wd[i] = ws[i];
        if (tid < 32) bsm[tid] = bias[coh * 32 + tid];
    }

    const uint32_t Xb = smem_u32(Xf);
    const int lane = tid & 31;
    const int grp = lane >> 2, q4 = lane & 3;
    const int pb = (tid >> 5) * 32;

    float acc[3][2][4][4];
#pragma unroll
    for (int s = 0; s < 3; s++)
#pragma unroll
        for (int mt = 0; mt < 2; mt++)
#pragma unroll
            for (int n = 0; n < 4; n++)
#pragma unroll
                for (int e = 0; e < 4; e++) acc[s][mt][n][e] = 0.f;

    // prologue: load strip r = y0-1 into slot 0
    {
        int rn = y0 - 1;
        int okr = (rn >= 0) ? 1 : 0;
        const char* rowp = (const char*)(inp + ((long)img * 256 + max(rn, 0)) * 16384);
        for (int i = tid; i < 4128; i += 256) {
            int p = i >> 4, c = i & 15;
            int gx = p - 1;
            int ok = (okr && (unsigned)gx < 256u) ? 16 : 0;
            const char* src = rowp + (uint32_t)min(max(gx, 0), 255) * 256u + (uint32_t)c * 16u;
            uint32_t dst = Xb + (uint32_t)p * 256u + (uint32_t)((c ^ (p & 7)) << 4);
            asm volatile("cp.async.cg.shared.global [%0], [%1], 16, %2;"
                         :: "r"(dst), "l"(src), "r"(ok));
        }
        asm volatile("cp.async.commit_group;" ::: "memory");
    }

    const int T = rows + 2;
    for (int s = 0; s < T; s += 3) {
        CONV_BODY(0, s);
        if (s + 1 < T) CONV_BODY(1, s + 1);
        if (s + 2 < T) CONV_BODY(2, s + 2);
    }
}

// ---------------- launch ----------------
extern "C" void kernel_launch(void* const* d_in, const int* in_sizes, int n_in,
                              void* d_out, int out_size) {
    const float* means      = (const float*)d_in[0];
    const float* gs_feats   = (const float*)d_in[2];
    const float* intrinsics = (const float*)d_in[3];
    const float* extrinsics = (const float*)d_in[4];
    const float* w1 = (const float*)d_in[5];
    const float* b1 = (const float*)d_in[6];
    const float* w2 = (const float*)d_in[7];
    const float* b2 = (const float*)d_in[8];
    float* out = (float*)d_out;

    const int smem = (18432 + 33024 + 32) * 4;  // 205,952 B
    cudaFuncSetAttribute(conv_mma<0>, cudaFuncAttributeMaxDynamicSharedMemorySize, smem);
    cudaFuncSetAttribute(conv_mma<1>, cudaFuncAttributeMaxDynamicSharedMemorySize, smem);

    setup_kernel<<<1, 256>>>(extrinsics, w1, w2);
    proj_kernel<<<dim3(256, 12), 256>>>(means, intrinsics);
    fuse_kernel<<<dim3(1024, 8), 256>>>(gs_feats);
    conv_mma<0><<<144, 256, smem>>>(b1, out);
    conv_mma<1><<<144, 256, smem>>>(b2, out);
}